// round 5
// baseline (speedup 1.0000x reference)
#include <cuda_runtime.h>
#include <cuda_bf16.h>
#include <mma.h>
#include <math.h>

using namespace nvcuda;

#define HID   128
#define NREL  8
#define MAXN  100000
#define MAXE  500000
#define BM    256
#define NTHR  512
#define LDA   (HID + 4)
#define GEMM_SMEM  ((BM + HID) * LDA * 4)            // 202752 B
#define EDGE_SMEM  (GEMM_SMEM + BM * 4)              // + sDst

// ---- scratch ----
__device__ float g_X0[(size_t)MAXN * HID];
__device__ float g_X1[(size_t)MAXN * HID];
__device__ int   g_cnt[MAXN * NREL];
__device__ int   g_rhist[NREL];
__device__ int   g_rbase[NREL + 1];
__device__ int   g_pos[NREL];
__device__ int   g_perm[MAXE];

// ---------------- setup kernels ----------------

__global__ void zero_kernel(int total) {
    int i = blockIdx.x * blockDim.x + threadIdx.x;
    if (i < total) g_cnt[i] = 0;
    if (i < NREL)  g_rhist[i] = 0;
}

__global__ void count_kernel(const int* __restrict__ dst,
                             const int* __restrict__ et, int E) {
    int e = blockIdx.x * blockDim.x + threadIdx.x;
    if (e < E) {
        int t = et[e];
        atomicAdd(&g_cnt[dst[e] * NREL + t], 1);
        atomicAdd(&g_rhist[t], 1);
    }
}

__global__ void prefix_kernel() {
    if (threadIdx.x == 0) {
        int acc = 0;
        g_rbase[0] = 0;
        for (int r = 0; r < NREL; r++) {
            g_pos[r] = acc;
            acc += g_rhist[r];
            g_rbase[r + 1] = acc;
        }
    }
}

__global__ void permute_kernel(const int* __restrict__ et, int E) {
    int e = blockIdx.x * blockDim.x + threadIdx.x;
    if (e < E) {
        int p = atomicAdd(&g_pos[et[e]], 1);
        g_perm[p] = e;
    }
}

__global__ void gather_kernel(const int* __restrict__ ids,
                              const float* __restrict__ emb, int N) {
    int n    = blockIdx.x * (blockDim.x >> 5) + (threadIdx.x >> 5);
    int lane = threadIdx.x & 31;
    if (n < N) {
        const float4* s = (const float4*)(emb + (size_t)ids[n] * HID);
        float4*       d = (float4*)(g_X0 + (size_t)n * HID);
        d[lane] = s[lane];
    }
}

// ---------------- root GEMM: C = X @ root ----------------
// 256x128 tile, 512 threads, 16 warps in 8x2 layout (32x64 per warp)

template <int LAYER>
__global__ __launch_bounds__(NTHR) void root_gemm_kernel(const float* __restrict__ root,
                                                         float* __restrict__ c_ext, int N) {
    extern __shared__ float smem[];
    float* sA = smem;
    float* sB = smem + BM * LDA;

    const float* X = (LAYER == 1) ? g_X0 : g_X1;
    float*       C = (LAYER == 1) ? g_X1 : c_ext;

    int row0 = blockIdx.x * BM;
    int tid  = threadIdx.x;

    for (int i = tid; i < BM * HID / 4; i += NTHR) {
        int r = i >> 5, c4 = i & 31;
        float4 v = make_float4(0.f, 0.f, 0.f, 0.f);
        if (row0 + r < N)
            v = ((const float4*)(X + (size_t)(row0 + r) * HID))[c4];
        float* d = sA + r * LDA + c4 * 4;
        d[0] = wmma::__float_to_tf32(v.x); d[1] = wmma::__float_to_tf32(v.y);
        d[2] = wmma::__float_to_tf32(v.z); d[3] = wmma::__float_to_tf32(v.w);
    }
    for (int i = tid; i < HID * HID / 4; i += NTHR) {
        int r = i >> 5, c4 = i & 31;
        float4 v = ((const float4*)(root + (size_t)r * HID))[c4];
        float* d = sB + r * LDA + c4 * 4;
        d[0] = wmma::__float_to_tf32(v.x); d[1] = wmma::__float_to_tf32(v.y);
        d[2] = wmma::__float_to_tf32(v.z); d[3] = wmma::__float_to_tf32(v.w);
    }
    __syncthreads();

    int warp = tid >> 5;
    int rw = warp >> 1, cw = warp & 1;

    wmma::fragment<wmma::accumulator, 16, 16, 8, float> acc[2][4];
    #pragma unroll
    for (int mi = 0; mi < 2; mi++)
        #pragma unroll
        for (int ni = 0; ni < 4; ni++) wmma::fill_fragment(acc[mi][ni], 0.0f);

    wmma::fragment<wmma::matrix_a, 16, 16, 8, wmma::precision::tf32, wmma::row_major> fa[2];
    wmma::fragment<wmma::matrix_b, 16, 16, 8, wmma::precision::tf32, wmma::row_major> fb[4];
    const float* aBase = sA + (rw * 32) * LDA;
    const float* bBase = sB + cw * 64;

    #pragma unroll
    for (int k = 0; k < HID; k += 8) {
        #pragma unroll
        for (int mi = 0; mi < 2; mi++)
            wmma::load_matrix_sync(fa[mi], aBase + mi * 16 * LDA + k, LDA);
        #pragma unroll
        for (int ni = 0; ni < 4; ni++)
            wmma::load_matrix_sync(fb[ni], bBase + k * LDA + ni * 16, LDA);
        #pragma unroll
        for (int mi = 0; mi < 2; mi++)
            #pragma unroll
            for (int ni = 0; ni < 4; ni++)
                wmma::mma_sync(acc[mi][ni], fa[mi], fb[ni], acc[mi][ni]);
    }

    #pragma unroll
    for (int mi = 0; mi < 2; mi++) {
        int orow = row0 + rw * 32 + mi * 16;
        if (orow + 16 <= N) {
            #pragma unroll
            for (int ni = 0; ni < 4; ni++)
                wmma::store_matrix_sync(C + (size_t)orow * HID + cw * 64 + ni * 16,
                                        acc[mi][ni], HID, wmma::mem_row_major);
        }
    }
}

// ---------------- fused edge GEMM + scatter ----------------
// Block = 256 edges of one relation. A[row] = x[src_e]/cnt[dst_e,r]; B = W_r.
// Epilogue: atomic-add C rows into out[dst_e].

template <int LAYER>
__global__ __launch_bounds__(NTHR) void edge_gemm_kernel(const float* __restrict__ W,
                                                         const int* __restrict__ src,
                                                         const int* __restrict__ dst,
                                                         float* __restrict__ out_ext,
                                                         int N) {
    extern __shared__ float smem[];
    float* sA   = smem;
    float* sB   = smem + BM * LDA;
    int*   sDst = (int*)(smem + (BM + HID) * LDA);

    const float* X   = (LAYER == 1) ? g_X0 : g_X1;
    float*       out = (LAYER == 1) ? g_X1 : out_ext;

    // map block -> (relation, tile)
    int blk = blockIdx.x;
    int rel = -1, start = 0, rend = 0;
    for (int rr = 0; rr < NREL; rr++) {
        int s0 = g_rbase[rr], s1 = g_rbase[rr + 1];
        int nt = (s1 - s0 + BM - 1) / BM;
        if (blk < nt) { rel = rr; start = s0 + blk * BM; rend = s1; break; }
        blk -= nt;
    }
    if (rel < 0) return;

    int tid  = threadIdx.x;
    int warp = tid >> 5;
    int lane = tid & 31;

    // gather A rows (16 warps x 16 rounds), fold 1/cnt into A
    for (int row = warp; row < BM; row += 16) {
        int gi = start + row;
        int sN = 0, dN = -1;
        float inv = 0.f;
        if (gi < rend) {
            int e = g_perm[gi];
            sN = src[e];
            dN = dst[e];
            inv = 1.0f / (float)g_cnt[dN * NREL + rel];
        }
        float4 v = ((const float4*)(X + (size_t)sN * HID))[lane];
        float* p = sA + row * LDA + lane * 4;
        p[0] = wmma::__float_to_tf32(v.x * inv);
        p[1] = wmma::__float_to_tf32(v.y * inv);
        p[2] = wmma::__float_to_tf32(v.z * inv);
        p[3] = wmma::__float_to_tf32(v.w * inv);
        if (lane == 0) sDst[row] = dN;
    }
    // B = W_rel
    const float* B = W + (size_t)rel * HID * HID;
    for (int i = tid; i < HID * HID / 4; i += NTHR) {
        int rr = i >> 5, c4 = i & 31;
        float4 v = ((const float4*)(B + (size_t)rr * HID))[c4];
        float* d = sB + rr * LDA + c4 * 4;
        d[0] = wmma::__float_to_tf32(v.x); d[1] = wmma::__float_to_tf32(v.y);
        d[2] = wmma::__float_to_tf32(v.z); d[3] = wmma::__float_to_tf32(v.w);
    }
    __syncthreads();

    int rw = warp >> 1, cw = warp & 1;

    wmma::fragment<wmma::accumulator, 16, 16, 8, float> acc[2][4];
    #pragma unroll
    for (int mi = 0; mi < 2; mi++)
        #pragma unroll
        for (int ni = 0; ni < 4; ni++) wmma::fill_fragment(acc[mi][ni], 0.0f);

    wmma::fragment<wmma::matrix_a, 16, 16, 8, wmma::precision::tf32, wmma::row_major> fa[2];
    wmma::fragment<wmma::matrix_b, 16, 16, 8, wmma::precision::tf32, wmma::row_major> fb[4];
    const float* aBase = sA + (rw * 32) * LDA;
    const float* bBase = sB + cw * 64;

    #pragma unroll
    for (int k = 0; k < HID; k += 8) {
        #pragma unroll
        for (int mi = 0; mi < 2; mi++)
            wmma::load_matrix_sync(fa[mi], aBase + mi * 16 * LDA + k, LDA);
        #pragma unroll
        for (int ni = 0; ni < 4; ni++)
            wmma::load_matrix_sync(fb[ni], bBase + k * LDA + ni * 16, LDA);
        #pragma unroll
        for (int mi = 0; mi < 2; mi++)
            #pragma unroll
            for (int ni = 0; ni < 4; ni++)
                wmma::mma_sync(acc[mi][ni], fa[mi], fb[ni], acc[mi][ni]);
    }

    // stage C in smem (overlay sA+sB), then atomic scatter
    __syncthreads();
    float* sC = smem;   // BM x HID = 128KB, fits inside the 198KB footprint
    #pragma unroll
    for (int mi = 0; mi < 2; mi++)
        #pragma unroll
        for (int ni = 0; ni < 4; ni++)
            wmma::store_matrix_sync(sC + (rw * 32 + mi * 16) * HID + cw * 64 + ni * 16,
                                    acc[mi][ni], HID, wmma::mem_row_major);
    __syncthreads();

    for (int row = warp; row < BM; row += 16) {
        int dN = sDst[row];
        if (dN < 0) continue;
        float4 v = ((const float4*)(sC + row * HID))[lane];
        float* o = out + (size_t)dN * HID + (size_t)lane * 4;
        asm volatile("red.global.add.v4.f32 [%0], {%1, %2, %3, %4};"
                     :: "l"(o), "f"(v.x), "f"(v.y), "f"(v.z), "f"(v.w)
                     : "memory");
    }
}

// ---------------- activations ----------------

__global__ void relu_bias_kernel(const float* __restrict__ bias, int total) {
    int i = blockIdx.x * blockDim.x + threadIdx.x;
    if (i < total) {
        float v = g_X1[i] + bias[i & (HID - 1)];
        g_X1[i] = v > 0.f ? v : 0.f;
    }
}

__global__ void sigmoid_bias_kernel(float* __restrict__ X,
                                    const float* __restrict__ bias, int total) {
    int i = blockIdx.x * blockDim.x + threadIdx.x;
    if (i < total) {
        float v = X[i] + bias[i & (HID - 1)];
        X[i] = 1.0f / (1.0f + expf(-v));
    }
}

// ---------------- launch ----------------

extern "C" void kernel_launch(void* const* d_in, const int* in_sizes, int n_in,
                              void* d_out, int out_size) {
    const int*   x_ids = (const int*)d_in[0];
    const int*   eidx  = (const int*)d_in[1];
    const int*   etype = (const int*)d_in[2];
    const float* emb   = (const float*)d_in[3];
    const float* W1    = (const float*)d_in[4];
    const float* root1 = (const float*)d_in[5];
    const float* b1    = (const float*)d_in[6];
    const float* W2    = (const float*)d_in[7];
    const float* root2 = (const float*)d_in[8];
    const float* b2    = (const float*)d_in[9];
    float*       out   = (float*)d_out;

    int N = in_sizes[0];
    int E = in_sizes[2];
    const int* src = eidx;
    const int* dst = eidx + E;
    int total_feat = N * HID;

    cudaFuncSetAttribute(root_gemm_kernel<1>, cudaFuncAttributeMaxDynamicSharedMemorySize, GEMM_SMEM);
    cudaFuncSetAttribute(root_gemm_kernel<2>, cudaFuncAttributeMaxDynamicSharedMemorySize, GEMM_SMEM);
    cudaFuncSetAttribute(edge_gemm_kernel<1>, cudaFuncAttributeMaxDynamicSharedMemorySize, EDGE_SMEM);
    cudaFuncSetAttribute(edge_gemm_kernel<2>, cudaFuncAttributeMaxDynamicSharedMemorySize, EDGE_SMEM);

    // counting sort of edges by relation + per-(dst,rel) counts
    zero_kernel<<<(N * NREL + 255) / 256, 256>>>(N * NREL);
    count_kernel<<<(E + 255) / 256, 256>>>(dst, etype, E);
    prefix_kernel<<<1, 32>>>();
    permute_kernel<<<(E + 255) / 256, 256>>>(etype, E);
    gather_kernel<<<(N + 7) / 8, 256>>>(x_ids, emb, N);

    int rblocks = (N + BM - 1) / BM;
    int eblocks = (E + BM - 1) / BM + NREL;

    // ---- layer 1 ----
    root_gemm_kernel<1><<<rblocks, NTHR, GEMM_SMEM>>>(root1, nullptr, N);
    edge_gemm_kernel<1><<<eblocks, NTHR, EDGE_SMEM>>>(W1, src, dst, nullptr, N);
    relu_bias_kernel<<<(total_feat + 255) / 256, 256>>>(b1, total_feat);

    // ---- layer 2 ----
    root_gemm_kernel<2><<<rblocks, NTHR, GEMM_SMEM>>>(root2, out, N);
    edge_gemm_kernel<2><<<eblocks, NTHR, EDGE_SMEM>>>(W2, src, dst, out, N);
    sigmoid_bias_kernel<<<(total_feat + 255) / 256, 256>>>(out, b2, total_feat);
}

// round 11
// speedup vs baseline: 1.4783x; 1.4783x over previous
#include <cuda_runtime.h>
#include <cuda_bf16.h>
#include <mma.h>
#include <math.h>

using namespace nvcuda;

#define HID   128
#define NREL  8
#define MAXN  100000
#define MAXE  500000
#define BM    256
#define NTHR  512
#define LDA   (HID + 4)
#define GEMM_SMEM  ((BM + HID) * LDA * 4)            // 202752 B
#define EDGE_SMEM  (GEMM_SMEM + BM * 4)              // + sDst

// ---- scratch ----
__device__ float g_X0[(size_t)MAXN * HID];
__device__ float g_X1[(size_t)MAXN * HID];
__device__ int   g_cnt[MAXN * NREL];
__device__ int   g_rhist[NREL];
__device__ int   g_rbase[NREL + 1];
__device__ int   g_pos[NREL];
__device__ int   g_perm[MAXE];

// ---------------- setup kernels ----------------

__global__ void zero_kernel(int total) {
    int i = blockIdx.x * blockDim.x + threadIdx.x;
    if (i < total) g_cnt[i] = 0;
    if (i < NREL)  g_rhist[i] = 0;
}

// per-(dst,rel) counts (spread atomics) + relation histogram (smem-aggregated)
__global__ void count_kernel(const int* __restrict__ dst,
                             const int* __restrict__ et, int E) {
    __shared__ int sh[NREL];
    if (threadIdx.x < NREL) sh[threadIdx.x] = 0;
    __syncthreads();
    int e = blockIdx.x * blockDim.x + threadIdx.x;
    if (e < E) {
        int t = et[e];
        atomicAdd(&g_cnt[dst[e] * NREL + t], 1);
        atomicAdd(&sh[t], 1);
    }
    __syncthreads();
    if (threadIdx.x < NREL && sh[threadIdx.x] > 0)
        atomicAdd(&g_rhist[threadIdx.x], sh[threadIdx.x]);
}

__global__ void prefix_kernel() {
    if (threadIdx.x == 0) {
        int acc = 0;
        g_rbase[0] = 0;
        for (int r = 0; r < NREL; r++) {
            g_pos[r] = acc;
            acc += g_rhist[r];
            g_rbase[r + 1] = acc;
        }
    }
}

// counting-sort scatter: block-level smem histogram gives in-block rank,
// one global atomicAdd per bin per block reserves the output range.
__global__ void permute_kernel(const int* __restrict__ et, int E) {
    __shared__ int sh[NREL];
    __shared__ int sbase[NREL];
    int tid = threadIdx.x;
    if (tid < NREL) sh[tid] = 0;
    __syncthreads();
    int e = blockIdx.x * blockDim.x + tid;
    int r = 0, rank = 0;
    bool valid = (e < E);
    if (valid) {
        r = et[e];
        rank = atomicAdd(&sh[r], 1);
    }
    __syncthreads();
    if (tid < NREL)
        sbase[tid] = (sh[tid] > 0) ? atomicAdd(&g_pos[tid], sh[tid]) : 0;
    __syncthreads();
    if (valid) g_perm[sbase[r] + rank] = e;
}

__global__ void gather_kernel(const int* __restrict__ ids,
                              const float* __restrict__ emb, int N) {
    int n    = blockIdx.x * (blockDim.x >> 5) + (threadIdx.x >> 5);
    int lane = threadIdx.x & 31;
    if (n < N) {
        const float4* s = (const float4*)(emb + (size_t)ids[n] * HID);
        float4*       d = (float4*)(g_X0 + (size_t)n * HID);
        d[lane] = s[lane];
    }
}

// ---------------- root GEMM: C = X @ root ----------------

template <int LAYER>
__global__ __launch_bounds__(NTHR) void root_gemm_kernel(const float* __restrict__ root,
                                                         float* __restrict__ c_ext, int N) {
    extern __shared__ float smem[];
    float* sA = smem;
    float* sB = smem + BM * LDA;

    const float* X = (LAYER == 1) ? g_X0 : g_X1;
    float*       C = (LAYER == 1) ? g_X1 : c_ext;

    int row0 = blockIdx.x * BM;
    int tid  = threadIdx.x;

    for (int i = tid; i < BM * HID / 4; i += NTHR) {
        int r = i >> 5, c4 = i & 31;
        float4 v = make_float4(0.f, 0.f, 0.f, 0.f);
        if (row0 + r < N)
            v = ((const float4*)(X + (size_t)(row0 + r) * HID))[c4];
        float* d = sA + r * LDA + c4 * 4;
        d[0] = wmma::__float_to_tf32(v.x); d[1] = wmma::__float_to_tf32(v.y);
        d[2] = wmma::__float_to_tf32(v.z); d[3] = wmma::__float_to_tf32(v.w);
    }
    for (int i = tid; i < HID * HID / 4; i += NTHR) {
        int r = i >> 5, c4 = i & 31;
        float4 v = ((const float4*)(root + (size_t)r * HID))[c4];
        float* d = sB + r * LDA + c4 * 4;
        d[0] = wmma::__float_to_tf32(v.x); d[1] = wmma::__float_to_tf32(v.y);
        d[2] = wmma::__float_to_tf32(v.z); d[3] = wmma::__float_to_tf32(v.w);
    }
    __syncthreads();

    int warp = tid >> 5;
    int rw = warp >> 1, cw = warp & 1;

    wmma::fragment<wmma::accumulator, 16, 16, 8, float> acc[2][4];
    #pragma unroll
    for (int mi = 0; mi < 2; mi++)
        #pragma unroll
        for (int ni = 0; ni < 4; ni++) wmma::fill_fragment(acc[mi][ni], 0.0f);

    wmma::fragment<wmma::matrix_a, 16, 16, 8, wmma::precision::tf32, wmma::row_major> fa[2];
    wmma::fragment<wmma::matrix_b, 16, 16, 8, wmma::precision::tf32, wmma::row_major> fb[4];
    const float* aBase = sA + (rw * 32) * LDA;
    const float* bBase = sB + cw * 64;

    #pragma unroll
    for (int k = 0; k < HID; k += 8) {
        #pragma unroll
        for (int mi = 0; mi < 2; mi++)
            wmma::load_matrix_sync(fa[mi], aBase + mi * 16 * LDA + k, LDA);
        #pragma unroll
        for (int ni = 0; ni < 4; ni++)
            wmma::load_matrix_sync(fb[ni], bBase + k * LDA + ni * 16, LDA);
        #pragma unroll
        for (int mi = 0; mi < 2; mi++)
            #pragma unroll
            for (int ni = 0; ni < 4; ni++)
                wmma::mma_sync(acc[mi][ni], fa[mi], fb[ni], acc[mi][ni]);
    }

    #pragma unroll
    for (int mi = 0; mi < 2; mi++) {
        int orow = row0 + rw * 32 + mi * 16;
        if (orow + 16 <= N) {
            #pragma unroll
            for (int ni = 0; ni < 4; ni++)
                wmma::store_matrix_sync(C + (size_t)orow * HID + cw * 64 + ni * 16,
                                        acc[mi][ni], HID, wmma::mem_row_major);
        }
    }
}

// ---------------- fused edge GEMM + scatter ----------------
// Block = 256 edges of one relation. A[row] = x[src_e]/cnt[dst_e,r]; B = W_r.
// Epilogue: atomic-add C rows into out[dst_e].

template <int LAYER>
__global__ __launch_bounds__(NTHR) void edge_gemm_kernel(const float* __restrict__ W,
                                                         const int* __restrict__ src,
                                                         const int* __restrict__ dst,
                                                         float* __restrict__ out_ext,
                                                         int N) {
    extern __shared__ float smem[];
    float* sA   = smem;
    float* sB   = smem + BM * LDA;
    int*   sDst = (int*)(smem + (BM + HID) * LDA);

    const float* X   = (LAYER == 1) ? g_X0 : g_X1;
    float*       out = (LAYER == 1) ? g_X1 : out_ext;

    // map block -> (relation, tile)
    int blk = blockIdx.x;
    int rel = -1, start = 0, rend = 0;
    for (int rr = 0; rr < NREL; rr++) {
        int s0 = g_rbase[rr], s1 = g_rbase[rr + 1];
        int nt = (s1 - s0 + BM - 1) / BM;
        if (blk < nt) { rel = rr; start = s0 + blk * BM; rend = s1; break; }
        blk -= nt;
    }
    if (rel < 0) return;

    int tid  = threadIdx.x;
    int warp = tid >> 5;
    int lane = tid & 31;

    // ---- gather A: each warp owns 16 contiguous rows ----
    // lanes 0..15 fetch metadata for the 16 rows in parallel, then shfl-broadcast.
    {
        int row0w = warp * 16;
        int sN = 0, dN = -1;
        float inv = 0.f;
        int gi = start + row0w + lane;
        if (lane < 16 && gi < rend) {
            int e = g_perm[gi];
            sN  = src[e];
            dN  = dst[e];
            inv = 1.0f / (float)g_cnt[dN * NREL + rel];
        }
        if (lane < 16) sDst[row0w + lane] = dN;

        #pragma unroll
        for (int i = 0; i < 16; i++) {
            int   s  = __shfl_sync(0xffffffffu, sN,  i);
            float iv = __shfl_sync(0xffffffffu, inv, i);
            float4 v = ((const float4*)(X + (size_t)s * HID))[lane];
            float* p = sA + (row0w + i) * LDA + lane * 4;
            p[0] = wmma::__float_to_tf32(v.x * iv);
            p[1] = wmma::__float_to_tf32(v.y * iv);
            p[2] = wmma::__float_to_tf32(v.z * iv);
            p[3] = wmma::__float_to_tf32(v.w * iv);
        }
    }
    // B = W_rel
    const float* B = W + (size_t)rel * HID * HID;
    for (int i = tid; i < HID * HID / 4; i += NTHR) {
        int rr = i >> 5, c4 = i & 31;
        float4 v = ((const float4*)(B + (size_t)rr * HID))[c4];
        float* d = sB + rr * LDA + c4 * 4;
        d[0] = wmma::__float_to_tf32(v.x); d[1] = wmma::__float_to_tf32(v.y);
        d[2] = wmma::__float_to_tf32(v.z); d[3] = wmma::__float_to_tf32(v.w);
    }
    __syncthreads();

    int rw = warp >> 1, cw = warp & 1;

    wmma::fragment<wmma::accumulator, 16, 16, 8, float> acc[2][4];
    #pragma unroll
    for (int mi = 0; mi < 2; mi++)
        #pragma unroll
        for (int ni = 0; ni < 4; ni++) wmma::fill_fragment(acc[mi][ni], 0.0f);

    wmma::fragment<wmma::matrix_a, 16, 16, 8, wmma::precision::tf32, wmma::row_major> fa[2];
    wmma::fragment<wmma::matrix_b, 16, 16, 8, wmma::precision::tf32, wmma::row_major> fb[4];
    const float* aBase = sA + (rw * 32) * LDA;
    const float* bBase = sB + cw * 64;

    #pragma unroll
    for (int k = 0; k < HID; k += 8) {
        #pragma unroll
        for (int mi = 0; mi < 2; mi++)
            wmma::load_matrix_sync(fa[mi], aBase + mi * 16 * LDA + k, LDA);
        #pragma unroll
        for (int ni = 0; ni < 4; ni++)
            wmma::load_matrix_sync(fb[ni], bBase + k * LDA + ni * 16, LDA);
        #pragma unroll
        for (int mi = 0; mi < 2; mi++)
            #pragma unroll
            for (int ni = 0; ni < 4; ni++)
                wmma::mma_sync(acc[mi][ni], fa[mi], fb[ni], acc[mi][ni]);
    }

    // stage C in smem (overlay sA+sB), then atomic scatter
    __syncthreads();
    float* sC = smem;   // BM x HID = 128KB inside the footprint
    #pragma unroll
    for (int mi = 0; mi < 2; mi++)
        #pragma unroll
        for (int ni = 0; ni < 4; ni++)
            wmma::store_matrix_sync(sC + (rw * 32 + mi * 16) * HID + cw * 64 + ni * 16,
                                    acc[mi][ni], HID, wmma::mem_row_major);
    __syncthreads();

    for (int row = warp; row < BM; row += 16) {
        int dN = sDst[row];
        if (dN < 0) continue;
        float4 v = ((const float4*)(sC + row * HID))[lane];
        float* o = out + (size_t)dN * HID + (size_t)lane * 4;
        asm volatile("red.global.add.v4.f32 [%0], {%1, %2, %3, %4};"
                     :: "l"(o), "f"(v.x), "f"(v.y), "f"(v.z), "f"(v.w)
                     : "memory");
    }
}

// ---------------- activations ----------------

__global__ void relu_bias_kernel(const float* __restrict__ bias, int total) {
    int i = blockIdx.x * blockDim.x + threadIdx.x;
    if (i < total) {
        float v = g_X1[i] + bias[i & (HID - 1)];
        g_X1[i] = v > 0.f ? v : 0.f;
    }
}

__global__ void sigmoid_bias_kernel(float* __restrict__ X,
                                    const float* __restrict__ bias, int total) {
    int i = blockIdx.x * blockDim.x + threadIdx.x;
    if (i < total) {
        float v = X[i] + bias[i & (HID - 1)];
        X[i] = 1.0f / (1.0f + expf(-v));
    }
}

// ---------------- launch ----------------

extern "C" void kernel_launch(void* const* d_in, const int* in_sizes, int n_in,
                              void* d_out, int out_size) {
    const int*   x_ids = (const int*)d_in[0];
    const int*   eidx  = (const int*)d_in[1];
    const int*   etype = (const int*)d_in[2];
    const float* emb   = (const float*)d_in[3];
    const float* W1    = (const float*)d_in[4];
    const float* root1 = (const float*)d_in[5];
    const float* b1    = (const float*)d_in[6];
    const float* W2    = (const float*)d_in[7];
    const float* root2 = (const float*)d_in[8];
    const float* b2    = (const float*)d_in[9];
    float*       out   = (float*)d_out;

    int N = in_sizes[0];
    int E = in_sizes[2];
    const int* src = eidx;
    const int* dst = eidx + E;
    int total_feat = N * HID;

    cudaFuncSetAttribute(root_gemm_kernel<1>, cudaFuncAttributeMaxDynamicSharedMemorySize, GEMM_SMEM);
    cudaFuncSetAttribute(root_gemm_kernel<2>, cudaFuncAttributeMaxDynamicSharedMemorySize, GEMM_SMEM);
    cudaFuncSetAttribute(edge_gemm_kernel<1>, cudaFuncAttributeMaxDynamicSharedMemorySize, EDGE_SMEM);
    cudaFuncSetAttribute(edge_gemm_kernel<2>, cudaFuncAttributeMaxDynamicSharedMemorySize, EDGE_SMEM);

    // counting sort of edges by relation + per-(dst,rel) counts
    zero_kernel<<<(N * NREL + 255) / 256, 256>>>(N * NREL);
    count_kernel<<<(E + 255) / 256, 256>>>(dst, etype, E);
    prefix_kernel<<<1, 32>>>();
    permute_kernel<<<(E + 255) / 256, 256>>>(etype, E);
    gather_kernel<<<(N + 7) / 8, 256>>>(x_ids, emb, N);

    int rblocks = (N + BM - 1) / BM;
    int eblocks = (E + BM - 1) / BM + NREL;

    // ---- layer 1 ----
    root_gemm_kernel<1><<<rblocks, NTHR, GEMM_SMEM>>>(root1, nullptr, N);
    edge_gemm_kernel<1><<<eblocks, NTHR, EDGE_SMEM>>>(W1, src, dst, nullptr, N);
    relu_bias_kernel<<<(total_feat + 255) / 256, 256>>>(b1, total_feat);

    // ---- layer 2 ----
    root_gemm_kernel<2><<<rblocks, NTHR, GEMM_SMEM>>>(root2, out, N);
    edge_gemm_kernel<2><<<eblocks, NTHR, EDGE_SMEM>>>(W2, src, dst, out, N);
    sigmoid_bias_kernel<<<(total_feat + 255) / 256, 256>>>(out, b2, total_feat);
}

// round 15
// speedup vs baseline: 1.7578x; 1.1891x over previous
#include <cuda_runtime.h>
#include <cuda_bf16.h>
#include <mma.h>
#include <math.h>

using namespace nvcuda;

#define HID   128
#define NREL  8
#define MAXN  100000
#define MAXE  500000
#define LDA   (HID + 4)

// ---- root GEMM config (unchanged: 256 rows, 512 thr) ----
#define RBM   256
#define RTHR  512
#define GEMM_SMEM  ((RBM + HID) * LDA * 4)           // 202752 B

// ---- edge GEMM config (128 rows, 256 thr, B in 2 K-halves) ----
#define EBM   128
#define ETHR  256
#define KHALF 64
#define EA_BYTES   (EBM * LDA * 4)                   // 67584
#define EB_BYTES   (KHALF * LDA * 4)                 // 33792
#define EDGE_SMEM  (EA_BYTES + EB_BYTES + EBM * 4)   // 101888 -> 2 blocks/SM

// ---- scratch ----
__device__ float g_X0[(size_t)MAXN * HID];
__device__ float g_X1[(size_t)MAXN * HID];
__device__ int   g_cnt[MAXN * NREL];
__device__ int   g_rhist[NREL];
__device__ int   g_rbase[NREL + 1];
__device__ int   g_pos[NREL];
__device__ int   g_perm[MAXE];

// ---------------- setup kernels ----------------

__global__ void zero_kernel(int total) {
    int i = blockIdx.x * blockDim.x + threadIdx.x;
    if (i < total) g_cnt[i] = 0;
    if (i < NREL)  g_rhist[i] = 0;
}

__global__ void count_kernel(const int* __restrict__ dst,
                             const int* __restrict__ et, int E) {
    __shared__ int sh[NREL];
    if (threadIdx.x < NREL) sh[threadIdx.x] = 0;
    __syncthreads();
    int e = blockIdx.x * blockDim.x + threadIdx.x;
    if (e < E) {
        int t = et[e];
        atomicAdd(&g_cnt[dst[e] * NREL + t], 1);
        atomicAdd(&sh[t], 1);
    }
    __syncthreads();
    if (threadIdx.x < NREL && sh[threadIdx.x] > 0)
        atomicAdd(&g_rhist[threadIdx.x], sh[threadIdx.x]);
}

__global__ void prefix_kernel() {
    if (threadIdx.x == 0) {
        int acc = 0;
        g_rbase[0] = 0;
        for (int r = 0; r < NREL; r++) {
            g_pos[r] = acc;
            acc += g_rhist[r];
            g_rbase[r + 1] = acc;
        }
    }
}

__global__ void permute_kernel(const int* __restrict__ et, int E) {
    __shared__ int sh[NREL];
    __shared__ int sbase[NREL];
    int tid = threadIdx.x;
    if (tid < NREL) sh[tid] = 0;
    __syncthreads();
    int e = blockIdx.x * blockDim.x + tid;
    int r = 0, rank = 0;
    bool valid = (e < E);
    if (valid) {
        r = et[e];
        rank = atomicAdd(&sh[r], 1);
    }
    __syncthreads();
    if (tid < NREL)
        sbase[tid] = (sh[tid] > 0) ? atomicAdd(&g_pos[tid], sh[tid]) : 0;
    __syncthreads();
    if (valid) g_perm[sbase[r] + rank] = e;
}

__global__ void gather_kernel(const int* __restrict__ ids,
                              const float* __restrict__ emb, int N) {
    int n    = blockIdx.x * (blockDim.x >> 5) + (threadIdx.x >> 5);
    int lane = threadIdx.x & 31;
    if (n < N) {
        const float4* s = (const float4*)(emb + (size_t)ids[n] * HID);
        float4*       d = (float4*)(g_X0 + (size_t)n * HID);
        d[lane] = s[lane];
    }
}

// ---------------- root GEMM: C = X @ root (unchanged) ----------------

template <int LAYER>
__global__ __launch_bounds__(RTHR) void root_gemm_kernel(const float* __restrict__ root,
                                                         float* __restrict__ c_ext, int N) {
    extern __shared__ float smem[];
    float* sA = smem;
    float* sB = smem + RBM * LDA;

    const float* X = (LAYER == 1) ? g_X0 : g_X1;
    float*       C = (LAYER == 1) ? g_X1 : c_ext;

    int row0 = blockIdx.x * RBM;
    int tid  = threadIdx.x;

    for (int i = tid; i < RBM * HID / 4; i += RTHR) {
        int r = i >> 5, c4 = i & 31;
        float4 v = make_float4(0.f, 0.f, 0.f, 0.f);
        if (row0 + r < N)
            v = ((const float4*)(X + (size_t)(row0 + r) * HID))[c4];
        float* d = sA + r * LDA + c4 * 4;
        d[0] = wmma::__float_to_tf32(v.x); d[1] = wmma::__float_to_tf32(v.y);
        d[2] = wmma::__float_to_tf32(v.z); d[3] = wmma::__float_to_tf32(v.w);
    }
    for (int i = tid; i < HID * HID / 4; i += RTHR) {
        int r = i >> 5, c4 = i & 31;
        float4 v = ((const float4*)(root + (size_t)r * HID))[c4];
        float* d = sB + r * LDA + c4 * 4;
        d[0] = wmma::__float_to_tf32(v.x); d[1] = wmma::__float_to_tf32(v.y);
        d[2] = wmma::__float_to_tf32(v.z); d[3] = wmma::__float_to_tf32(v.w);
    }
    __syncthreads();

    int warp = tid >> 5;
    int rw = warp >> 1, cw = warp & 1;

    wmma::fragment<wmma::accumulator, 16, 16, 8, float> acc[2][4];
    #pragma unroll
    for (int mi = 0; mi < 2; mi++)
        #pragma unroll
        for (int ni = 0; ni < 4; ni++) wmma::fill_fragment(acc[mi][ni], 0.0f);

    wmma::fragment<wmma::matrix_a, 16, 16, 8, wmma::precision::tf32, wmma::row_major> fa[2];
    wmma::fragment<wmma::matrix_b, 16, 16, 8, wmma::precision::tf32, wmma::row_major> fb[4];
    const float* aBase = sA + (rw * 32) * LDA;
    const float* bBase = sB + cw * 64;

    #pragma unroll
    for (int k = 0; k < HID; k += 8) {
        #pragma unroll
        for (int mi = 0; mi < 2; mi++)
            wmma::load_matrix_sync(fa[mi], aBase + mi * 16 * LDA + k, LDA);
        #pragma unroll
        for (int ni = 0; ni < 4; ni++)
            wmma::load_matrix_sync(fb[ni], bBase + k * LDA + ni * 16, LDA);
        #pragma unroll
        for (int mi = 0; mi < 2; mi++)
            #pragma unroll
            for (int ni = 0; ni < 4; ni++)
                wmma::mma_sync(acc[mi][ni], fa[mi], fb[ni], acc[mi][ni]);
    }

    #pragma unroll
    for (int mi = 0; mi < 2; mi++) {
        int orow = row0 + rw * 32 + mi * 16;
        if (orow + 16 <= N) {
            #pragma unroll
            for (int ni = 0; ni < 4; ni++)
                wmma::store_matrix_sync(C + (size_t)orow * HID + cw * 64 + ni * 16,
                                        acc[mi][ni], HID, wmma::mem_row_major);
        }
    }
}

// ---------------- fused edge GEMM + scatter ----------------
// Block = 128 edges of one relation, 256 threads (8 warps, 4x2 layout).
// B = W_rel streamed in two K=64 halves (small smem -> 2 blocks/SM).

template <int LAYER>
__global__ __launch_bounds__(ETHR, 2) void edge_gemm_kernel(const float* __restrict__ W,
                                                            const int* __restrict__ src,
                                                            const int* __restrict__ dst,
                                                            float* __restrict__ out_ext,
                                                            int N) {
    extern __shared__ float smem[];
    float* sA   = smem;                                  // [EBM][LDA]
    float* sB   = smem + EBM * LDA;                      // [KHALF][LDA]
    int*   sDst = (int*)(smem + EBM * LDA + KHALF * LDA);

    const float* X   = (LAYER == 1) ? g_X0 : g_X1;
    float*       out = (LAYER == 1) ? g_X1 : out_ext;

    // map block -> (relation, tile)
    int blk = blockIdx.x;
    int rel = -1, start = 0, rend = 0;
    for (int rr = 0; rr < NREL; rr++) {
        int s0 = g_rbase[rr], s1 = g_rbase[rr + 1];
        int nt = (s1 - s0 + EBM - 1) / EBM;
        if (blk < nt) { rel = rr; start = s0 + blk * EBM; rend = s1; break; }
        blk -= nt;
    }
    if (rel < 0) return;

    int tid  = threadIdx.x;
    int warp = tid >> 5;
    int lane = tid & 31;

    // ---- gather A: each of 8 warps owns 16 rows; metadata fetched by
    //      lanes 0..15 in parallel, then shfl-broadcast.
    {
        int row0w = warp * 16;
        int sN = 0, dN = -1;
        float inv = 0.f;
        int gi = start + row0w + lane;
        if (lane < 16 && gi < rend) {
            int e = g_perm[gi];
            sN  = src[e];
            dN  = dst[e];
            inv = 1.0f / (float)g_cnt[dN * NREL + rel];
        }
        if (lane < 16) sDst[row0w + lane] = dN;

        #pragma unroll
        for (int i = 0; i < 16; i++) {
            int   s  = __shfl_sync(0xffffffffu, sN,  i);
            float iv = __shfl_sync(0xffffffffu, inv, i);
            float4 v = ((const float4*)(X + (size_t)s * HID))[lane];
            float* p = sA + (row0w + i) * LDA + lane * 4;
            p[0] = wmma::__float_to_tf32(v.x * iv);
            p[1] = wmma::__float_to_tf32(v.y * iv);
            p[2] = wmma::__float_to_tf32(v.z * iv);
            p[3] = wmma::__float_to_tf32(v.w * iv);
        }
    }

    const float* B = W + (size_t)rel * HID * HID;
    int rw = warp >> 1, cw = warp & 1;   // 4x2 warp layout, 32x64 tiles

    wmma::fragment<wmma::accumulator, 16, 16, 8, float> acc[2][4];
    #pragma unroll
    for (int mi = 0; mi < 2; mi++)
        #pragma unroll
        for (int ni = 0; ni < 4; ni++) wmma::fill_fragment(acc[mi][ni], 0.0f);

    wmma::fragment<wmma::matrix_a, 16, 16, 8, wmma::precision::tf32, wmma::row_major> fa[2];
    wmma::fragment<wmma::matrix_b, 16, 16, 8, wmma::precision::tf32, wmma::row_major> fb[4];
    const float* aBase = sA + (rw * 32) * LDA;
    const float* bBase = sB + cw * 64;

    // ---- two K-halves: load B rows [ph*64, ph*64+64) then 8 MMA k-steps ----
    #pragma unroll
    for (int ph = 0; ph < 2; ph++) {
        __syncthreads();   // previous phase's reads of sB done (and A ready on ph=0)
        for (int i = tid; i < KHALF * HID / 4; i += ETHR) {
            int r = i >> 5, c4 = i & 31;
            float4 v = ((const float4*)(B + (size_t)(ph * KHALF + r) * HID))[c4];
            float* d = sB + r * LDA + c4 * 4;
            d[0] = wmma::__float_to_tf32(v.x); d[1] = wmma::__float_to_tf32(v.y);
            d[2] = wmma::__float_to_tf32(v.z); d[3] = wmma::__float_to_tf32(v.w);
        }
        __syncthreads();

        #pragma unroll
        for (int k = 0; k < KHALF; k += 8) {
            int ka = ph * KHALF + k;   // k index into A (full K in smem)
            #pragma unroll
            for (int mi = 0; mi < 2; mi++)
                wmma::load_matrix_sync(fa[mi], aBase + mi * 16 * LDA + ka, LDA);
            #pragma unroll
            for (int ni = 0; ni < 4; ni++)
                wmma::load_matrix_sync(fb[ni], bBase + k * LDA + ni * 16, LDA);
            #pragma unroll
            for (int mi = 0; mi < 2; mi++)
                #pragma unroll
                for (int ni = 0; ni < 4; ni++)
                    wmma::mma_sync(acc[mi][ni], fa[mi], fb[ni], acc[mi][ni]);
        }
    }

    // ---- stage C in smem (overlay sA; 64KB < 66KB), then atomic scatter ----
    __syncthreads();
    float* sC = smem;
    #pragma unroll
    for (int mi = 0; mi < 2; mi++)
        #pragma unroll
        for (int ni = 0; ni < 4; ni++)
            wmma::store_matrix_sync(sC + (rw * 32 + mi * 16) * HID + cw * 64 + ni * 16,
                                    acc[mi][ni], HID, wmma::mem_row_major);
    __syncthreads();

    for (int row = warp; row < EBM; row += 8) {
        int dN = sDst[row];
        if (dN < 0) continue;
        float4 v = ((const float4*)(sC + row * HID))[lane];
        float* o = out + (size_t)dN * HID + (size_t)lane * 4;
        asm volatile("red.global.add.v4.f32 [%0], {%1, %2, %3, %4};"
                     :: "l"(o), "f"(v.x), "f"(v.y), "f"(v.z), "f"(v.w)
                     : "memory");
    }
}

// ---------------- activations ----------------

__global__ void relu_bias_kernel(const float* __restrict__ bias, int total) {
    int i = blockIdx.x * blockDim.x + threadIdx.x;
    if (i < total) {
        float v = g_X1[i] + bias[i & (HID - 1)];
        g_X1[i] = v > 0.f ? v : 0.f;
    }
}

__global__ void sigmoid_bias_kernel(float* __restrict__ X,
                                    const float* __restrict__ bias, int total) {
    int i = blockIdx.x * blockDim.x + threadIdx.x;
    if (i < total) {
        float v = X[i] + bias[i & (HID - 1)];
        X[i] = 1.0f / (1.0f + expf(-v));
    }
}

// ---------------- launch ----------------

extern "C" void kernel_launch(void* const* d_in, const int* in_sizes, int n_in,
                              void* d_out, int out_size) {
    const int*   x_ids = (const int*)d_in[0];
    const int*   eidx  = (const int*)d_in[1];
    const int*   etype = (const int*)d_in[2];
    const float* emb   = (const float*)d_in[3];
    const float* W1    = (const float*)d_in[4];
    const float* root1 = (const float*)d_in[5];
    const float* b1    = (const float*)d_in[6];
    const float* W2    = (const float*)d_in[7];
    const float* root2 = (const float*)d_in[8];
    const float* b2    = (const float*)d_in[9];
    float*       out   = (float*)d_out;

    int N = in_sizes[0];
    int E = in_sizes[2];
    const int* src = eidx;
    const int* dst = eidx + E;
    int total_feat = N * HID;

    cudaFuncSetAttribute(root_gemm_kernel<1>, cudaFuncAttributeMaxDynamicSharedMemorySize, GEMM_SMEM);
    cudaFuncSetAttribute(root_gemm_kernel<2>, cudaFuncAttributeMaxDynamicSharedMemorySize, GEMM_SMEM);
    cudaFuncSetAttribute(edge_gemm_kernel<1>, cudaFuncAttributeMaxDynamicSharedMemorySize, EDGE_SMEM);
    cudaFuncSetAttribute(edge_gemm_kernel<2>, cudaFuncAttributeMaxDynamicSharedMemorySize, EDGE_SMEM);

    // counting sort of edges by relation + per-(dst,rel) counts
    zero_kernel<<<(N * NREL + 255) / 256, 256>>>(N * NREL);
    count_kernel<<<(E + 255) / 256, 256>>>(dst, etype, E);
    prefix_kernel<<<1, 32>>>();
    permute_kernel<<<(E + 255) / 256, 256>>>(etype, E);
    gather_kernel<<<(N + 7) / 8, 256>>>(x_ids, emb, N);

    int rblocks = (N + RBM - 1) / RBM;
    int eblocks = (E + EBM - 1) / EBM + NREL;

    // ---- layer 1 ----
    root_gemm_kernel<1><<<rblocks, RTHR, GEMM_SMEM>>>(root1, nullptr, N);
    edge_gemm_kernel<1><<<eblocks, ETHR, EDGE_SMEM>>>(W1, src, dst, nullptr, N);
    relu_bias_kernel<<<(total_feat + 255) / 256, 256>>>(b1, total_feat);

    // ---- layer 2 ----
    root_gemm_kernel<2><<<rblocks, RTHR, GEMM_SMEM>>>(root2, out, N);
    edge_gemm_kernel<2><<<eblocks, ETHR, EDGE_SMEM>>>(W2, src, dst, out, N);
    sigmoid_bias_kernel<<<(total_feat + 255) / 256, 256>>>(out, b2, total_feat);
}